// round 1
// baseline (speedup 1.0000x reference)
#include <cuda_runtime.h>
#include <cstdint>

// QConv2d: new_rho[b] = U @ rho_big[b] @ U^T, U = kron(uc, kron(ux, uy))
// With B=256, D=8, C_IN=2, C_OUT=4:
//   rho_big[:,128:,128:] = rho (channel insertion is x -> x+128)
//   => new_rho[(c,P),(c',P')] = sum_{e,e'} cc[c,e] cc[c',e'] A[(e,P),(e',P')]
//      cc[c,e] = uc[c, e+2],  A = (I2 (x) ux (x) uy) rho (I2 (x) ux (x) uy)^T
// Separable: 4 passes of 8-deep 1-D transforms + channel expansion epilogue.

#define STRIDE 129   // 128 + 1: conflict-free for both row- and column-parallel access
#define NB 256       // batches
#define NT 256       // threads per CTA

__global__ __launch_bounds__(NT, 1)
void qconv2d_kernel(const float* __restrict__ rho,
                    const float* __restrict__ ux,
                    const float* __restrict__ uy,
                    const float* __restrict__ uc,
                    float* __restrict__ out) {
    extern __shared__ float sm[];
    float* A   = sm;                 // 128*129 floats
    float* Bf  = sm + 128 * STRIDE;  // 128*129 floats
    float* sux = sm + 2 * 128 * STRIDE;       // 64
    float* suy = sux + 64;                     // 64
    float* scc = suy + 64;                     // 8: scc[c*2+e] = uc[c, e+2]

    const int t = threadIdx.x;
    const int b = blockIdx.x;

    if (t < 64)  sux[t] = ux[t];
    if (t >= 64 && t < 128) suy[t - 64] = uy[t - 64];
    if (t < 8) { int c = t >> 1, e = t & 1; scc[t] = uc[c * 4 + 2 + e]; }

    // ---- Load rho[b] (128x128) into A (stride 129). Coalesced scalar loads,
    // conflict-free STS (warp covers consecutive columns of one row).
    const float* rb = rho + (size_t)b * 16384;
#pragma unroll
    for (int k = 0; k < 64; k++) {
        int idx = t + NT * k;
        A[(idx >> 7) * STRIDE + (idx & 127)] = rb[idx];
    }
    __syncthreads();

    // ---- Pass 1 (rows, uy over j): Bf[(e,i,kj), s] = sum_j uy[kj,j] A[(e,i,j), s]
#pragma unroll 1
    for (int g = 0; g < 8; g++) {
        int pair = t + NT * g;        // 2048 (group,s) pairs
        int s  = pair & 127;          // column (warp-consecutive -> conflict-free)
        int gi = pair >> 7;           // (e,i) in 0..15, warp-uniform
        float in[8];
#pragma unroll
        for (int j = 0; j < 8; j++) in[j] = A[(gi * 8 + j) * STRIDE + s];
#pragma unroll
        for (int k = 0; k < 8; k++) {
            float acc = 0.f;
#pragma unroll
            for (int j = 0; j < 8; j++) acc += suy[k * 8 + j] * in[j];
            Bf[(gi * 8 + k) * STRIDE + s] = acc;
        }
    }
    __syncthreads();

    // ---- Pass 2 (rows, ux over i): A[(e,ki,kj), s] = sum_i ux[ki,i] Bf[(e,i,kj), s]
#pragma unroll 1
    for (int g = 0; g < 8; g++) {
        int pair = t + NT * g;
        int s  = pair & 127;
        int gk = pair >> 7;           // (e,kj)
        int e = gk >> 3, kj = gk & 7;
        float in[8];
#pragma unroll
        for (int i = 0; i < 8; i++) in[i] = Bf[(e * 64 + i * 8 + kj) * STRIDE + s];
#pragma unroll
        for (int k = 0; k < 8; k++) {
            float acc = 0.f;
#pragma unroll
            for (int i = 0; i < 8; i++) acc += sux[k * 8 + i] * in[i];
            A[(e * 64 + k * 8 + kj) * STRIDE + s] = acc;
        }
    }
    __syncthreads();

    // ---- Pass 3 (cols, uy over j'): Bf[r,(e',i',kj')] = sum_j' A[r,(e',i',j')] uy[kj',j']
    // Row-parallel: warp threads take consecutive r; stride 129 -> conflict-free.
#pragma unroll 1
    for (int g = 0; g < 8; g++) {
        int pair = t + NT * g;
        int r  = pair & 127;          // warp-consecutive rows
        int cg = pair >> 7;           // (e',i') warp-uniform
        float in[8];
#pragma unroll
        for (int j = 0; j < 8; j++) in[j] = A[r * STRIDE + cg * 8 + j];
#pragma unroll
        for (int k = 0; k < 8; k++) {
            float acc = 0.f;
#pragma unroll
            for (int j = 0; j < 8; j++) acc += suy[k * 8 + j] * in[j];
            Bf[r * STRIDE + cg * 8 + k] = acc;
        }
    }
    __syncthreads();

    // ---- Pass 4 (cols, ux over i'): A[r,(e',ki',kj')] = sum_i' Bf[r,(e',i',kj')] ux[ki',i']
#pragma unroll 1
    for (int g = 0; g < 8; g++) {
        int pair = t + NT * g;
        int r  = pair & 127;
        int gk = pair >> 7;           // (e',kj')
        int e2 = gk >> 3, kj = gk & 7;
        float in[8];
#pragma unroll
        for (int i = 0; i < 8; i++) in[i] = Bf[r * STRIDE + e2 * 64 + i * 8 + kj];
#pragma unroll
        for (int k = 0; k < 8; k++) {
            float acc = 0.f;
#pragma unroll
            for (int i = 0; i < 8; i++) acc += sux[k * 8 + i] * in[i];
            A[r * STRIDE + e2 * 64 + k * 8 + kj] = acc;
        }
    }
    __syncthreads();

    // ---- Epilogue: channel expansion + coalesced store.
    // out[b, c*64+P, c'*64+P'], thread t owns output column t = (c', P').
    const int cp = t >> 6;            // c'
    const int Pp = t & 63;            // P'
    const float k0 = scc[cp * 2 + 0]; // cc[c', 0]
    const float k1 = scc[cp * 2 + 1]; // cc[c', 1]
    const float c00 = scc[0], c01 = scc[1];
    const float c10 = scc[2], c11 = scc[3];
    const float c20 = scc[4], c21 = scc[5];
    const float c30 = scc[6], c31 = scc[7];
    float* ob = out + (size_t)b * 65536 + t;
#pragma unroll 4
    for (int P = 0; P < 64; P++) {
        float a00 = A[P * STRIDE + Pp];            // (e=0,P),(e'=0,P')
        float a01 = A[P * STRIDE + 64 + Pp];       // (e=0),(e'=1)
        float a10 = A[(64 + P) * STRIDE + Pp];     // (e=1),(e'=0)
        float a11 = A[(64 + P) * STRIDE + 64 + Pp];
        float v0 = k0 * a00 + k1 * a01;            // sum over e' for e=0
        float v1 = k0 * a10 + k1 * a11;            // e=1
        ob[(size_t)(0 * 64 + P) * 256] = c00 * v0 + c01 * v1;
        ob[(size_t)(1 * 64 + P) * 256] = c10 * v0 + c11 * v1;
        ob[(size_t)(2 * 64 + P) * 256] = c20 * v0 + c21 * v1;
        ob[(size_t)(3 * 64 + P) * 256] = c30 * v0 + c31 * v1;
    }
}

extern "C" void kernel_launch(void* const* d_in, const int* in_sizes, int n_in,
                              void* d_out, int out_size) {
    const float* rho = (const float*)d_in[0];   // [256,128,128]
    const float* ux  = (const float*)d_in[1];   // [8,8]
    const float* uy  = (const float*)d_in[2];   // [8,8]
    const float* uc  = (const float*)d_in[3];   // [4,4]
    float* out = (float*)d_out;                 // [256,256,256]

    const size_t smem = (2 * 128 * STRIDE + 64 + 64 + 8) * sizeof(float); // ~132.6 KB
    cudaFuncSetAttribute(qconv2d_kernel,
                         cudaFuncAttributeMaxDynamicSharedMemorySize, (int)smem);
    qconv2d_kernel<<<NB, NT, smem>>>(rho, ux, uy, uc, out);
}

// round 2
// speedup vs baseline: 1.4747x; 1.4747x over previous
#include <cuda_runtime.h>
#include <cstdint>

// QConv2d on GB300: new_rho = U rho_big U^T, U = kron(uc, ux (x) uy).
// rho_big[:,128:,128:] = rho  =>  new_rho[(c,P),(c',P')] =
//   sum_{e,e'} cc[c,e] cc[c',e'] A[(e,P),(e',P')],  cc[c,e]=uc[c,e+2],
//   A = (I2 (x) ux (x) uy) rho (I2 (x) ux (x) uy)^T   (4 separable 8-deep passes).
// In-place single smem buffer (stride 132, 16B-aligned rows), float4 smem/gmem
// traffic, f32x2 packed FMA, 3 CTAs/SM -> whole grid in one wave.

#define ST 132
#define NT 256

typedef unsigned long long u64;

__device__ __forceinline__ u64 pk2(float a, float b) {
    u64 r; asm("mov.b64 %0,{%1,%2};" : "=l"(r) : "f"(a), "f"(b)); return r;
}
__device__ __forceinline__ u64 mul2(u64 a, u64 b) {
    u64 r; asm("mul.rn.f32x2 %0,%1,%2;" : "=l"(r) : "l"(a), "l"(b)); return r;
}
__device__ __forceinline__ void fma2(u64& d, u64 a, u64 b) {
    asm("fma.rn.f32x2 %0,%1,%2,%0;" : "+l"(d) : "l"(a), "l"(b));
}

extern __shared__ float smf[];

__global__ __launch_bounds__(NT, 3)
void qconv2d_kernel(const float* __restrict__ rho,
                    const float* __restrict__ ux,
                    const float* __restrict__ uy,
                    const float* __restrict__ uc,
                    float* __restrict__ out) {
    float* A    = smf;                         // 128*132 floats (67584 B)
    u64*   uxd  = (u64*)(smf + 128 * ST);      // 64: (ux[k,i], ux[k,i])
    u64*   uyd  = uxd + 64;                    // 64: (uy[k,j], uy[k,j])
    u64*   uypp = uyd + 64;                    // 32: (uy[2kp,j], uy[2kp+1,j])
    float* scc  = (float*)(uypp + 32);         // 8:  cc[c*2+e] = uc[c, e+2]

    const int t = threadIdx.x;
    const int b = blockIdx.x;

    if (t < 64) { float vx = ux[t], vy = uy[t]; uxd[t] = pk2(vx, vx); uyd[t] = pk2(vy, vy); }
    if (t >= 64 && t < 96) {
        int m = t - 64, kp = m >> 3, j = m & 7;
        uypp[m] = pk2(uy[(2 * kp) * 8 + j], uy[(2 * kp + 1) * 8 + j]);
    }
    if (t >= 96 && t < 104) { int m = t - 96; scc[m] = uc[(m >> 1) * 4 + 2 + (m & 1)]; }

    // ---- Load rho[b] (128x128) as float4, STS.128 into stride-132 layout.
    const float4* rb4 = (const float4*)(rho + (size_t)b * 16384);
#pragma unroll
    for (int k = 0; k < 16; k++) {
        int idx = t + NT * k;                    // 0..4095 float4s
        int row = idx >> 5, c4 = idx & 31;
        *(float4*)&A[row * ST + 4 * c4] = rb4[idx];
    }
    __syncthreads();

    // ---- Pass 1 (rows, uy over j): row = gi*8 + j -> gi*8 + kj, in-place.
#pragma unroll 1
    for (int it = 0; it < 2; it++) {
        int task = t + NT * it;
        int s4 = task & 31, gi = task >> 5;      // gi = (e,i) 0..15
        ulonglong2 in[8];
#pragma unroll
        for (int j = 0; j < 8; j++) in[j] = *(ulonglong2*)&A[(gi * 8 + j) * ST + 4 * s4];
#pragma unroll
        for (int k = 0; k < 8; k++) {
            u64 c0 = uyd[k * 8];
            u64 ax = mul2(c0, in[0].x), ay = mul2(c0, in[0].y);
#pragma unroll
            for (int j = 1; j < 8; j++) { u64 c = uyd[k * 8 + j]; fma2(ax, c, in[j].x); fma2(ay, c, in[j].y); }
            ulonglong2 o; o.x = ax; o.y = ay;
            *(ulonglong2*)&A[(gi * 8 + k) * ST + 4 * s4] = o;
        }
    }
    __syncthreads();

    // ---- Pass 2 (rows, ux over i): row = e*64 + i*8 + kj -> e*64 + k*8 + kj.
#pragma unroll 1
    for (int it = 0; it < 2; it++) {
        int task = t + NT * it;
        int s4 = task & 31, rem = task >> 5;
        int kj = rem & 7, e = rem >> 3;
        ulonglong2 in[8];
#pragma unroll
        for (int i = 0; i < 8; i++) in[i] = *(ulonglong2*)&A[(e * 64 + i * 8 + kj) * ST + 4 * s4];
#pragma unroll
        for (int k = 0; k < 8; k++) {
            u64 c0 = uxd[k * 8];
            u64 ax = mul2(c0, in[0].x), ay = mul2(c0, in[0].y);
#pragma unroll
            for (int i = 1; i < 8; i++) { u64 c = uxd[k * 8 + i]; fma2(ax, c, in[i].x); fma2(ay, c, in[i].y); }
            ulonglong2 o; o.x = ax; o.y = ay;
            *(ulonglong2*)&A[(e * 64 + k * 8 + kj) * ST + 4 * s4] = o;
        }
    }
    __syncthreads();

    // ---- Pass 3 (cols, uy over j'): col = cg*8 + j' -> cg*8 + kj'. Paired outputs.
#pragma unroll 1
    for (int it = 0; it < 8; it++) {
        int task = t + NT * it;
        int r = task & 127, cg = task >> 7;      // cg = (e',i') 0..15
        float4 p = *(float4*)&A[r * ST + cg * 8];
        float4 q = *(float4*)&A[r * ST + cg * 8 + 4];
        u64 d0 = pk2(p.x, p.x), d1 = pk2(p.y, p.y), d2 = pk2(p.z, p.z), d3 = pk2(p.w, p.w);
        u64 d4 = pk2(q.x, q.x), d5 = pk2(q.y, q.y), d6 = pk2(q.z, q.z), d7 = pk2(q.w, q.w);
        u64 o[4];
#pragma unroll
        for (int kp = 0; kp < 4; kp++) {
            u64 acc = mul2(uypp[kp * 8 + 0], d0);
            fma2(acc, uypp[kp * 8 + 1], d1); fma2(acc, uypp[kp * 8 + 2], d2);
            fma2(acc, uypp[kp * 8 + 3], d3); fma2(acc, uypp[kp * 8 + 4], d4);
            fma2(acc, uypp[kp * 8 + 5], d5); fma2(acc, uypp[kp * 8 + 6], d6);
            fma2(acc, uypp[kp * 8 + 7], d7);
            o[kp] = acc;
        }
        ulonglong2 w0, w1; w0.x = o[0]; w0.y = o[1]; w1.x = o[2]; w1.y = o[3];
        *(ulonglong2*)&A[r * ST + cg * 8] = w0;
        *(ulonglong2*)&A[r * ST + cg * 8 + 4] = w1;
    }
    __syncthreads();

    // ---- Pass 4 (cols, ux over i'): col = e2*64 + i*8 + kj, vectorized over kj quad.
#pragma unroll 1
    for (int it = 0; it < 2; it++) {
        int task = t + NT * it;
        int r = task & 127, rem = task >> 7;
        int kjq = rem & 1, e2 = rem >> 1;
        int base = r * ST + e2 * 64 + 4 * kjq;
        ulonglong2 in[8];
#pragma unroll
        for (int i = 0; i < 8; i++) in[i] = *(ulonglong2*)&A[base + 8 * i];
#pragma unroll
        for (int k = 0; k < 8; k++) {
            u64 c0 = uxd[k * 8];
            u64 ax = mul2(c0, in[0].x), ay = mul2(c0, in[0].y);
#pragma unroll
            for (int i = 1; i < 8; i++) { u64 c = uxd[k * 8 + i]; fma2(ax, c, in[i].x); fma2(ay, c, in[i].y); }
            ulonglong2 o; o.x = ax; o.y = ay;
            *(ulonglong2*)&A[base + 8 * k] = o;
        }
    }
    __syncthreads();

    // ---- Epilogue: channel expansion, STG.128 coalesced.
    // Thread t -> output cols cp*64 + 4q..+3, rows P in [rr*16, rr*16+16), all c.
    const int q  = t & 15;
    const int cp = (t >> 4) & 3;
    const int rr = t >> 6;
    u64 k0d = pk2(scc[cp * 2], scc[cp * 2]);
    u64 k1d = pk2(scc[cp * 2 + 1], scc[cp * 2 + 1]);
    u64 c0d[4], c1d[4];
#pragma unroll
    for (int c = 0; c < 4; c++) {
        c0d[c] = pk2(scc[c * 2], scc[c * 2]);
        c1d[c] = pk2(scc[c * 2 + 1], scc[c * 2 + 1]);
    }
    float* ob = out + (size_t)b * 65536 + cp * 64 + 4 * q;
#pragma unroll 1
    for (int pp = 0; pp < 16; pp++) {
        int P = rr * 16 + pp;
        ulonglong2 a00 = *(ulonglong2*)&A[P * ST + 4 * q];
        ulonglong2 a01 = *(ulonglong2*)&A[P * ST + 64 + 4 * q];
        ulonglong2 a10 = *(ulonglong2*)&A[(64 + P) * ST + 4 * q];
        ulonglong2 a11 = *(ulonglong2*)&A[(64 + P) * ST + 64 + 4 * q];
        u64 v0x = mul2(k0d, a00.x); fma2(v0x, k1d, a01.x);
        u64 v0y = mul2(k0d, a00.y); fma2(v0y, k1d, a01.y);
        u64 v1x = mul2(k0d, a10.x); fma2(v1x, k1d, a11.x);
        u64 v1y = mul2(k0d, a10.y); fma2(v1y, k1d, a11.y);
#pragma unroll
        for (int c = 0; c < 4; c++) {
            u64 ox = mul2(c0d[c], v0x); fma2(ox, c1d[c], v1x);
            u64 oy = mul2(c0d[c], v0y); fma2(oy, c1d[c], v1y);
            ulonglong2 w; w.x = ox; w.y = oy;
            *(ulonglong2*)&ob[(size_t)(c * 64 + P) * 256] = w;
        }
    }
}

extern "C" void kernel_launch(void* const* d_in, const int* in_sizes, int n_in,
                              void* d_out, int out_size) {
    const float* rho = (const float*)d_in[0];   // [256,128,128]
    const float* ux  = (const float*)d_in[1];   // [8,8]
    const float* uy  = (const float*)d_in[2];   // [8,8]
    const float* uc  = (const float*)d_in[3];   // [4,4]
    float* out = (float*)d_out;                 // [256,256,256]

    const size_t smem = (128 * ST) * sizeof(float) + (64 + 64 + 32) * sizeof(u64)
                      + 8 * sizeof(float);      // ~68.9 KB -> 3 CTAs/SM
    cudaFuncSetAttribute(qconv2d_kernel,
                         cudaFuncAttributeMaxDynamicSharedMemorySize, (int)smem);
    qconv2d_kernel<<<256, NT, smem>>>(rho, ux, uy, uc, out);
}